// round 2
// baseline (speedup 1.0000x reference)
#include <cuda_runtime.h>
#include <math.h>

#define BGRAPH  32768
#define NPG     54
#define EPG     144
#define NTOT    (BGRAPH*NPG)
#define ETOT    (BGRAPH*EPG)
#define OSTRIDE 232            // 226 used, padded to multiple of 8

// Scratch for concat([embeds(216), g(10)]) per graph.
__device__ __align__(16) float g_scratch[(size_t)BGRAPH * OSTRIDE];

// ---------- packed fp32x2 helpers (FFMA2 path, sm_103a) ----------
__device__ __forceinline__ void ffma2(unsigned long long& d,
                                      unsigned long long a,
                                      unsigned long long b) {
    asm("fma.rn.f32x2 %0, %1, %2, %0;" : "+l"(d) : "l"(a), "l"(b));
}
__device__ __forceinline__ unsigned long long pack2(float lo, float hi) {
    unsigned long long r;
    asm("mov.b64 %0, {%1, %2};" : "=l"(r) : "f"(lo), "f"(hi));
    return r;
}
__device__ __forceinline__ void unpack2(float& lo, float& hi, unsigned long long v) {
    asm("mov.b64 {%0, %1}, %2;" : "=f"(lo), "=f"(hi) : "l"(v));
}

// ============================================================================
// Kernel 1: one CTA per graph. Entire GNN in shared memory.
// ============================================================================
// sW packing offsets (floats):
//  Wrel1:0(128) Wroot1:128(128) b1:256(16) Wrel2:272(64) Wroot2:336(64)
//  b2:400(4) Wg1:404(80) bg1:484(8) Wg2:492(64) bg2:556(8) Wg3:564(80) bg3:644(10)
__global__ void __launch_bounds__(128) gnn_kernel(
    const float* __restrict__ x,  const int* __restrict__ ei,
    const float* __restrict__ ea, const float* __restrict__ gf,
    const float* __restrict__ Wrel1, const float* __restrict__ b1,
    const float* __restrict__ Wroot1,
    const float* __restrict__ Wrel2, const float* __restrict__ b2,
    const float* __restrict__ Wroot2,
    const float* __restrict__ Wg1, const float* __restrict__ bg1,
    const float* __restrict__ Wg2, const float* __restrict__ bg2,
    const float* __restrict__ Wg3, const float* __restrict__ bg3)
{
    __shared__ __align__(16) float sx[NPG * 8];     // node features (8-wide)
    __shared__ __align__(16) float sh1[NPG * 16];   // hidden layer 1
    __shared__ __align__(16) float sagg[NPG * 16];  // aggregation buffer (8- then 16-wide)
    __shared__ float sattr[EPG];
    __shared__ int   ssrc[EPG];
    __shared__ int   shead[NPG];
    __shared__ int   snext[EPG];
    __shared__ float sW[654];
    __shared__ float sgf[10];

    const int b   = blockIdx.x;
    const int tid = threadIdx.x;
    const int nbase = b * NPG;
    const int ebase = b * EPG;

    // ---- cooperative loads ----
    {
        const float* xg = x + (size_t)nbase * 8;
        for (int i = tid; i < NPG * 8; i += 128) sx[i] = xg[i];
        if (tid < NPG) shead[tid] = -1;
        // weights
        sW[tid]       = Wrel1[tid];     // 128
        sW[128 + tid] = Wroot1[tid];    // 128
        if (tid < 16) sW[256 + tid] = b1[tid];
        if (tid < 64) { sW[272 + tid] = Wrel2[tid]; sW[336 + tid] = Wroot2[tid]; }
        if (tid < 4)  sW[400 + tid] = b2[tid];
        if (tid < 80) sW[404 + tid] = Wg1[tid];
        if (tid < 8)  sW[484 + tid] = bg1[tid];
        if (tid < 64) sW[492 + tid] = Wg2[tid];
        if (tid < 8)  sW[556 + tid] = bg2[tid];
        if (tid < 80) sW[564 + tid] = Wg3[tid];
        if (tid < 10) sW[644 + tid] = bg3[tid];
        if (tid < 10) sgf[tid] = gf[b * 10 + tid];
    }
    __syncthreads();   // shead must be -1 before list build

    // ---- build per-destination edge linked lists (144 atomicExch) ----
    for (int e = tid; e < EPG; e += 128) {
        int s = ei[ebase + e] - nbase;            // src (local)
        int d = ei[ETOT + ebase + e] - nbase;     // dst (local)
        ssrc[e]  = s;
        sattr[e] = ea[ebase + e];
        snext[e] = atomicExch(&shead[d], e);
    }
    __syncthreads();

    // ---- conv1 aggregation: agg[d][0:8] = sum attr * x[src] ----
    if (tid < NPG * 2) {                     // (node, float4-chunk)
        int d = tid >> 1, c = tid & 1;
        float4 acc = make_float4(0.f, 0.f, 0.f, 0.f);
        for (int e = shead[d]; e >= 0; e = snext[e]) {
            float a = sattr[e];
            float4 xv = reinterpret_cast<const float4*>(sx)[ssrc[e] * 2 + c];
            acc.x += a * xv.x; acc.y += a * xv.y;
            acc.z += a * xv.z; acc.w += a * xv.w;
        }
        reinterpret_cast<float4*>(sagg)[tid] = acc;   // 8-wide rows
    }
    __syncthreads();

    // ---- lin1: h1 = relu(agg @ Wrel1 + b1 + x @ Wroot1)  [54x16] ----
    for (int i = tid; i < NPG * 16; i += 128) {
        int n = i >> 4, j = i & 15;
        const float4* ar4 = reinterpret_cast<const float4*>(sagg) + n * 2;
        const float4* xr4 = reinterpret_cast<const float4*>(sx) + n * 2;
        float4 a0 = ar4[0], a1 = ar4[1], x0 = xr4[0], x1 = xr4[1];
        float acc = sW[256 + j];
        acc += a0.x * sW[0*16+j] + a0.y * sW[1*16+j] + a0.z * sW[2*16+j] + a0.w * sW[3*16+j];
        acc += a1.x * sW[4*16+j] + a1.y * sW[5*16+j] + a1.z * sW[6*16+j] + a1.w * sW[7*16+j];
        acc += x0.x * sW[128+0*16+j] + x0.y * sW[128+1*16+j] + x0.z * sW[128+2*16+j] + x0.w * sW[128+3*16+j];
        acc += x1.x * sW[128+4*16+j] + x1.y * sW[128+5*16+j] + x1.z * sW[128+6*16+j] + x1.w * sW[128+7*16+j];
        sh1[i] = fmaxf(acc, 0.f);
    }
    __syncthreads();

    // ---- conv2 aggregation: agg[d][0:16] = sum attr * h1[src] ----
    for (int i = tid; i < NPG * 4; i += 128) {   // (node, float4-chunk of 16)
        int d = i >> 2, c = i & 3;
        float4 acc = make_float4(0.f, 0.f, 0.f, 0.f);
        for (int e = shead[d]; e >= 0; e = snext[e]) {
            float a = sattr[e];
            float4 hv = reinterpret_cast<const float4*>(sh1)[ssrc[e] * 4 + c];
            acc.x += a * hv.x; acc.y += a * hv.y;
            acc.z += a * hv.z; acc.w += a * hv.w;
        }
        reinterpret_cast<float4*>(sagg)[i] = acc;   // 16-wide rows
    }
    __syncthreads();

    float* og = g_scratch + (size_t)b * OSTRIDE;

    if (tid < 32) {
        // ---- warp 0: global MLP 10 -> 8 -> 8 -> 10 via shuffles ----
        int lane = tid;
        int l8  = lane & 7;
        int l10 = (lane < 10) ? lane : 0;
        float a1v = sW[484 + l8];
        #pragma unroll
        for (int k = 0; k < 10; k++) a1v += sgf[k] * sW[404 + k * 8 + l8];
        float s1 = fmaxf(a1v, 0.f);

        float a2v = sW[556 + l8];
        #pragma unroll
        for (int k = 0; k < 8; k++)
            a2v += __shfl_sync(0xffffffffu, s1, k) * sW[492 + k * 8 + l8];
        float s2 = fmaxf(a2v, 0.f);

        float a3v = sW[644 + l10];
        #pragma unroll
        for (int k = 0; k < 8; k++)
            a3v += __shfl_sync(0xffffffffu, s2, k) * sW[564 + k * 10 + l10];
        if (lane < 10) og[216 + lane] = fmaxf(a3v, 0.f);
    } else {
        // ---- warps 1-3: lin2 -> write embeds [54x4] directly to scratch ----
        for (int i = tid - 32; i < NPG * 4; i += 96) {
            int n = i >> 2, j = i & 3;
            const float* ar = sagg + n * 16;
            const float* hr = sh1 + n * 16;
            float acc = sW[400 + j];
            #pragma unroll
            for (int k = 0; k < 16; k++)
                acc += ar[k] * sW[272 + k * 4 + j] + hr[k] * sW[336 + k * 4 + j];
            og[i] = fmaxf(acc, 0.f);
        }
    }
}

// ============================================================================
// Kernel 2: batched out-MLP. 32 graphs per CTA, 128 threads (thread = column j).
// o128 = relu(out226 @ Wo1 + bo1);  out = sigmoid(o128 @ Wo2 + bo2)
// ============================================================================
__global__ void __launch_bounds__(128) mlp_kernel(
    const float* __restrict__ Wo1, const float* __restrict__ bo1,
    const float* __restrict__ Wo2, const float* __restrict__ bo2,
    float* __restrict__ out)
{
    __shared__ __align__(16) float sG[32 * OSTRIDE];   // 29,696 B
    __shared__ float sRed[4][32];

    const int tid = threadIdx.x;
    const int b0  = blockIdx.x * 32;

    // stage 32 rows of scratch: layout identical -> straight linear copy
    {
        const float4* src4 = reinterpret_cast<const float4*>(g_scratch) + (size_t)b0 * (OSTRIDE / 4);
        float4* dst4 = reinterpret_cast<float4*>(sG);
        for (int i = tid; i < 32 * (OSTRIDE / 4); i += 128) dst4[i] = src4[i];
    }
    __syncthreads();

    unsigned long long acc[32];
    #pragma unroll
    for (int g = 0; g < 32; g++) acc[g] = 0ull;

    const float* wcol = Wo1 + tid;     // column j = tid of [226,128]
    for (int kc = 0; kc < 224; kc += 8) {
        float w0 = wcol[(kc + 0) * 128], w1 = wcol[(kc + 1) * 128];
        float w2 = wcol[(kc + 2) * 128], w3 = wcol[(kc + 3) * 128];
        float w4 = wcol[(kc + 4) * 128], w5 = wcol[(kc + 5) * 128];
        float w6 = wcol[(kc + 6) * 128], w7 = wcol[(kc + 7) * 128];
        unsigned long long wp0 = pack2(w0, w1), wp1 = pack2(w2, w3);
        unsigned long long wp2 = pack2(w4, w5), wp3 = pack2(w6, w7);
        #pragma unroll
        for (int g = 0; g < 32; g++) {
            const ulonglong2* p = reinterpret_cast<const ulonglong2*>(sG + g * OSTRIDE + kc);
            ulonglong2 va = p[0];
            ulonglong2 vb = p[1];
            ffma2(acc[g], va.x, wp0);
            ffma2(acc[g], va.y, wp1);
            ffma2(acc[g], vb.x, wp2);
            ffma2(acc[g], vb.y, wp3);
        }
    }
    {   // tail: k = 224, 225
        unsigned long long wp = pack2(wcol[224 * 128], wcol[225 * 128]);
        #pragma unroll
        for (int g = 0; g < 32; g++) {
            unsigned long long v = *reinterpret_cast<const unsigned long long*>(sG + g * OSTRIDE + 224);
            ffma2(acc[g], v, wp);
        }
    }

    const float bj   = bo1[tid];
    const float w2j  = Wo2[tid];
    const float bo2v = bo2[0];

    __syncthreads();   // done reading sG; reuse for partial products
    #pragma unroll
    for (int g = 0; g < 32; g++) {
        float lo, hi; unpack2(lo, hi, acc[g]);
        float p = fmaxf(lo + hi + bj, 0.f) * w2j;
        sG[tid * 33 + g] = p;        // stride 33: conflict-free
    }
    __syncthreads();

    {   // reduce over j: 4 quarters of 32 columns each
        int g = tid & 31, q = tid >> 5;
        float s = 0.f;
        #pragma unroll
        for (int jj = 0; jj < 32; jj++) s += sG[(q * 32 + jj) * 33 + g];
        sRed[q][g] = s;
    }
    __syncthreads();
    if (tid < 32) {
        float z = sRed[0][tid] + sRed[1][tid] + sRed[2][tid] + sRed[3][tid] + bo2v;
        out[b0 + tid] = 1.f / (1.f + expf(-z));
    }
}

// ============================================================================
extern "C" void kernel_launch(void* const* d_in, const int* in_sizes, int n_in,
                              void* d_out, int out_size) {
    (void)in_sizes; (void)n_in; (void)out_size;
    const float* x      = (const float*)d_in[0];
    const int*   ei     = (const int*)  d_in[1];
    const float* ea     = (const float*)d_in[2];
    const float* gfeats = (const float*)d_in[3];
    const float* Wrel1  = (const float*)d_in[4];
    const float* b1     = (const float*)d_in[5];
    const float* Wroot1 = (const float*)d_in[6];
    const float* Wrel2  = (const float*)d_in[7];
    const float* b2     = (const float*)d_in[8];
    const float* Wroot2 = (const float*)d_in[9];
    const float* Wg1    = (const float*)d_in[10];
    const float* bg1    = (const float*)d_in[11];
    const float* Wg2    = (const float*)d_in[12];
    const float* bg2    = (const float*)d_in[13];
    const float* Wg3    = (const float*)d_in[14];
    const float* bg3    = (const float*)d_in[15];
    const float* Wo1    = (const float*)d_in[16];
    const float* bo1    = (const float*)d_in[17];
    const float* Wo2    = (const float*)d_in[18];
    const float* bo2    = (const float*)d_in[19];
    float* out = (float*)d_out;

    gnn_kernel<<<BGRAPH, 128>>>(x, ei, ea, gfeats,
                                Wrel1, b1, Wroot1, Wrel2, b2, Wroot2,
                                Wg1, bg1, Wg2, bg2, Wg3, bg3);
    mlp_kernel<<<BGRAPH / 32, 128>>>(Wo1, bo1, Wo2, bo2, out);
}